// round 15
// baseline (speedup 1.0000x reference)
#include <cuda_runtime.h>
#include <cuda_bf16.h>
#include <cstdint>

#define B_ 2
#define S_ 2048
#define E_ 1024
#define H_ 16
#define D_ 64
#define M_ (B_*S_)   // 4096 rows

// Scratch (device globals; no allocation)
__device__ float g_Q[M_*E_];
__device__ float g_K[M_*E_];
__device__ float g_V[M_*E_];
__device__ float g_A[M_*E_];
__device__ __align__(16) __nv_bfloat16 g_qhi[M_*E_];
__device__ __align__(16) __nv_bfloat16 g_qlo[M_*E_];
__device__ __align__(16) __nv_bfloat16 g_khi[M_*E_];
__device__ __align__(16) __nv_bfloat16 g_klo[M_*E_];
__device__ __align__(16) __nv_bfloat16 g_vhi[M_*E_];
__device__ __align__(16) __nv_bfloat16 g_vlo[M_*E_];
__device__ __align__(16) __nv_bfloat16 g_ahi[M_*E_];
__device__ __align__(16) __nv_bfloat16 g_alo[M_*E_];
__device__ __align__(16) __nv_bfloat16 g_whi[4][E_*E_];
__device__ __align__(16) __nv_bfloat16 g_wlo[4][E_*E_];
// splits of the PROJECTED Q and K (written by QKV GEMM epilogue)
__device__ __align__(16) __nv_bfloat16 g_pqh[M_*E_];
__device__ __align__(16) __nv_bfloat16 g_pql[M_*E_];
__device__ __align__(16) __nv_bfloat16 g_pkh[M_*E_];
__device__ __align__(16) __nv_bfloat16 g_pkl[M_*E_];

// ---------------- PTX helpers ----------------------------------------------
__device__ __forceinline__ uint32_t smem_u32(const void* p) {
    uint32_t a;
    asm("{ .reg .u64 t; cvta.to.shared.u64 t, %1; cvt.u32.u64 %0, t; }"
        : "=r"(a) : "l"(p));
    return a;
}
__device__ __forceinline__ void cp16(uint32_t dst, const void* src) {
    asm volatile("cp.async.cg.shared.global [%0], [%1], 16;" :: "r"(dst), "l"(src));
}
#define CP_COMMIT() asm volatile("cp.async.commit_group;" ::: "memory")
#define CP_WAIT0()  asm volatile("cp.async.wait_group 0;" ::: "memory")
#define BAR(id, cnt) asm volatile("bar.sync %0, %1;" :: "r"(id), "r"(cnt) : "memory")
#define BAR_ARRIVE(id, cnt) asm volatile("bar.arrive %0, %1;" :: "r"(id), "r"(cnt) : "memory")
#define MEMBAR_CTA() asm volatile("membar.cta;" ::: "memory")

__device__ __forceinline__ void ldsm_x4(uint32_t& r0, uint32_t& r1,
                                        uint32_t& r2, uint32_t& r3, uint32_t addr) {
    asm volatile("ldmatrix.sync.aligned.m8n8.x4.shared.b16 {%0,%1,%2,%3}, [%4];"
                 : "=r"(r0), "=r"(r1), "=r"(r2), "=r"(r3) : "r"(addr));
}
__device__ __forceinline__ void mma_bf16(float* d, const uint32_t* a,
                                         uint32_t b0, uint32_t b1) {
    asm volatile(
        "mma.sync.aligned.m16n8k16.row.col.f32.bf16.bf16.f32 "
        "{%0,%1,%2,%3}, {%4,%5,%6,%7}, {%8,%9}, {%0,%1,%2,%3};"
        : "+f"(d[0]), "+f"(d[1]), "+f"(d[2]), "+f"(d[3])
        : "r"(a[0]), "r"(a[1]), "r"(a[2]), "r"(a[3]), "r"(b0), "r"(b1));
}
__device__ __forceinline__ uint32_t sw128(uint32_t off) {
    return off ^ ((off >> 3) & 0x70);
}

// ---------------------------------------------------------------------------
// Batched splits: fp32 -> (hi, lo) bf16.
// ---------------------------------------------------------------------------
__device__ __forceinline__ void split_one(const float* __restrict__ x,
                                          __nv_bfloat16* __restrict__ hi,
                                          __nv_bfloat16* __restrict__ lo, int i)
{
    float4 v = ((const float4*)x)[i];
    __nv_bfloat16 h0 = __float2bfloat16(v.x);
    __nv_bfloat16 h1 = __float2bfloat16(v.y);
    __nv_bfloat16 h2 = __float2bfloat16(v.z);
    __nv_bfloat16 h3 = __float2bfloat16(v.w);
    __nv_bfloat16 l0 = __float2bfloat16(v.x - __bfloat162float(h0));
    __nv_bfloat16 l1 = __float2bfloat16(v.y - __bfloat162float(h1));
    __nv_bfloat16 l2 = __float2bfloat16(v.z - __bfloat162float(h2));
    __nv_bfloat16 l3 = __float2bfloat16(v.w - __bfloat162float(h3));
    __nv_bfloat162 ph0; ph0.x = h0; ph0.y = h1;
    __nv_bfloat162 ph1; ph1.x = h2; ph1.y = h3;
    __nv_bfloat162 pl0; pl0.x = l0; pl0.y = l1;
    __nv_bfloat162 pl1; pl1.x = l2; pl1.y = l3;
    ((__nv_bfloat162*)hi)[i*2]   = ph0;
    ((__nv_bfloat162*)hi)[i*2+1] = ph1;
    ((__nv_bfloat162*)lo)[i*2]   = pl0;
    ((__nv_bfloat162*)lo)[i*2+1] = pl1;
}

__global__ __launch_bounds__(256)
void split3(const float* __restrict__ q, const float* __restrict__ k,
            const float* __restrict__ v,
            __nv_bfloat16* qh, __nv_bfloat16* ql, __nv_bfloat16* kh,
            __nv_bfloat16* kl, __nv_bfloat16* vh, __nv_bfloat16* vl, int n4)
{
    int i = blockIdx.x * blockDim.x + threadIdx.x;
    if (i >= n4) return;
    int z = blockIdx.y;
    const float* x = (z == 0) ? q : (z == 1) ? k : v;
    __nv_bfloat16* hi = (z == 0) ? qh : (z == 1) ? kh : vh;
    __nv_bfloat16* lo = (z == 0) ? ql : (z == 1) ? kl : vl;
    split_one(x, hi, lo, i);
}

__global__ __launch_bounds__(256)
void split4(const float* __restrict__ w0, const float* __restrict__ w1,
            const float* __restrict__ w2, const float* __restrict__ w3,
            __nv_bfloat16* h0, __nv_bfloat16* l0, __nv_bfloat16* h1, __nv_bfloat16* l1,
            __nv_bfloat16* h2, __nv_bfloat16* l2, __nv_bfloat16* h3, __nv_bfloat16* l3,
            int n4)
{
    int i = blockIdx.x * blockDim.x + threadIdx.x;
    if (i >= n4) return;
    int z = blockIdx.y;
    const float* x = (z == 0) ? w0 : (z == 1) ? w1 : (z == 2) ? w2 : w3;
    __nv_bfloat16* hi = (z == 0) ? h0 : (z == 1) ? h1 : (z == 2) ? h2 : h3;
    __nv_bfloat16* lo = (z == 0) ? l0 : (z == 1) ? l1 : (z == 2) ? l2 : l3;
    split_one(x, hi, lo, i);
}

// ---------------------------------------------------------------------------
// HYBRID GEMM tile body (128x128): warps 0-7 FFMA K[512,1024) with register
// software pipeline; warps 8-15 HMMA 3-slab bf16 K[0,512).
// ---------------------------------------------------------------------------
#define KF0 512
#define T_NIT 24
#define ATILE_B (128*128)
#define STAGE_B (2*ATILE_B)
#define STAG_F  (128*132)
#define HY_DSMEM (STAG_F*4)

__device__ __forceinline__ void hy_load_tiles(
    const __nv_bfloat16* __restrict__ Ap, const __nv_bfloat16* __restrict__ Bp,
    int m0, int n0, int kc, uint32_t sa, uint32_t sbb, int t)
{
#pragma unroll
    for (int i = 0; i < 4; i++) {
        int cidx = t + i*256;
        int row = cidx >> 3;
        int cb  = (cidx & 7) * 16;
        uint32_t sw = sw128((uint32_t)(row*128 + cb));
        cp16(sa  + sw, (const char*)(Ap + (size_t)(m0+row)*E_ + kc) + cb);
        cp16(sbb + sw, (const char*)(Bp + (size_t)(n0+row)*E_ + kc) + cb);
    }
}

__device__ __forceinline__ void gemm_tile(
    const float* __restrict__ A, const float* __restrict__ W,
    const __nv_bfloat16* __restrict__ Ahi, const __nv_bfloat16* __restrict__ Alo,
    const __nv_bfloat16* __restrict__ Whi, const __nv_bfloat16* __restrict__ Wlo,
    float* __restrict__ C, __nv_bfloat16* Chi, __nv_bfloat16* Clo,
    int m0, int n0, char* dsm, float (*As)[132], float (*Bs)[132])
{
    float* stag = (float*)dsm;
    const uint32_t sb = smem_u32(dsm);
    const int tid = threadIdx.x;
    const int wid = tid >> 5;
    const int lane = tid & 31;

    if (wid < 8) {
        const int t  = tid;
        const int tx = t & 15;
        const int ty = t >> 4;
        const int tm = ty * 8;
        const int tn = tx * 8;
        const int lr = t >> 2;
        const int lk = (t & 3) * 4;

        float acc[8][8];
#pragma unroll
        for (int i = 0; i < 8; i++)
#pragma unroll
            for (int j = 0; j < 8; j++) acc[i][j] = 0.f;

        const float* Ap0 = &A[(size_t)(m0 + lr) * E_];
        const float* Ap1 = &A[(size_t)(m0 + lr + 64) * E_];
        const float* Bp0 = &W[(size_t)(n0 + lr) * E_];
        const float* Bp1 = &W[(size_t)(n0 + lr + 64) * E_];

        // prologue prefetch (chunk 0)
        float4 pa0 = *(const float4*)(Ap0 + KF0 + lk);
        float4 pa1 = *(const float4*)(Ap1 + KF0 + lk);
        float4 pb0 = *(const float4*)(Bp0 + KF0 + lk);
        float4 pb1 = *(const float4*)(Bp1 + KF0 + lk);

        for (int k0 = KF0; k0 < E_; k0 += 16) {
            // stage current chunk from registers
            As[lk + 0][lr] = pa0.x; As[lk + 1][lr] = pa0.y;
            As[lk + 2][lr] = pa0.z; As[lk + 3][lr] = pa0.w;
            As[lk + 0][lr + 64] = pa1.x; As[lk + 1][lr + 64] = pa1.y;
            As[lk + 2][lr + 64] = pa1.z; As[lk + 3][lr + 64] = pa1.w;
            Bs[lk + 0][lr] = pb0.x; Bs[lk + 1][lr] = pb0.y;
            Bs[lk + 2][lr] = pb0.z; Bs[lk + 3][lr] = pb0.w;
            Bs[lk + 0][lr + 64] = pb1.x; Bs[lk + 1][lr + 64] = pb1.y;
            Bs[lk + 2][lr + 64] = pb1.z; Bs[lk + 3][lr + 64] = pb1.w;
            // prefetch next chunk (latency hidden under barrier + compute)
            if (k0 + 16 < E_) {
                pa0 = *(const float4*)(Ap0 + k0 + 16 + lk);
                pa1 = *(const float4*)(Ap1 + k0 + 16 + lk);
                pb0 = *(const float4*)(Bp0 + k0 + 16 + lk);
                pb1 = *(const float4*)(Bp1 + k0 + 16 + lk);
            }
            BAR(1, 256);
#pragma unroll
            for (int kk = 0; kk < 16; kk++) {
                float a[8], b[8];
                float4 tt;
                tt = *(const float4*)&As[kk][tm];     a[0]=tt.x; a[1]=tt.y; a[2]=tt.z; a[3]=tt.w;
                tt = *(const float4*)&As[kk][tm + 4]; a[4]=tt.x; a[5]=tt.y; a[6]=tt.z; a[7]=tt.w;
                tt = *(const float4*)&Bs[kk][tn];     b[0]=tt.x; b[1]=tt.y; b[2]=tt.z; b[3]=tt.w;
                tt = *(const float4*)&Bs[kk][tn + 4]; b[4]=tt.x; b[5]=tt.y; b[6]=tt.z; b[7]=tt.w;
#pragma unroll
                for (int i = 0; i < 8; i++)
#pragma unroll
                    for (int j = 0; j < 8; j++)
                        acc[i][j] = fmaf(a[i], b[j], acc[i][j]);
            }
            BAR(1, 256);
        }

        BAR(0, 512);

#pragma unroll
        for (int i = 0; i < 8; i++) {
            const float* sp = &stag[(tm + i) * 132 + tn];
            float4 s0 = *(const float4*)&sp[0];
            float4 s1 = *(const float4*)&sp[4];
            float r0 = acc[i][0] + s0.x, r1 = acc[i][1] + s0.y;
            float r2 = acc[i][2] + s0.z, r3 = acc[i][3] + s0.w;
            float r4 = acc[i][4] + s1.x, r5 = acc[i][5] + s1.y;
            float r6 = acc[i][6] + s1.z, r7 = acc[i][7] + s1.w;
            size_t idx = (size_t)(m0 + tm + i) * E_ + n0 + tn;
            *(float4*)&C[idx]     = make_float4(r0, r1, r2, r3);
            *(float4*)&C[idx + 4] = make_float4(r4, r5, r6, r7);
            if (Chi) {
                float rv[8] = {r0, r1, r2, r3, r4, r5, r6, r7};
#pragma unroll
                for (int p = 0; p < 4; p++) {
                    __nv_bfloat16 h0 = __float2bfloat16(rv[p*2]);
                    __nv_bfloat16 h1 = __float2bfloat16(rv[p*2+1]);
                    __nv_bfloat162 ph; ph.x = h0; ph.y = h1;
                    __nv_bfloat162 pl;
                    pl.x = __float2bfloat16(rv[p*2]   - __bfloat162float(h0));
                    pl.y = __float2bfloat16(rv[p*2+1] - __bfloat162float(h1));
                    *(__nv_bfloat162*)&Chi[idx + p*2] = ph;
                    *(__nv_bfloat162*)&Clo[idx + p*2] = pl;
                }
            }
        }
    } else {
        const int t = tid - 256;
        const int wt = wid - 8;
        const int wm = (wt & 1) * 64;
        const int wn = (wt >> 1) * 32;

        float acc[4][4][4];
#pragma unroll
        for (int mi = 0; mi < 4; mi++)
#pragma unroll
            for (int ni = 0; ni < 4; ni++)
#pragma unroll
                for (int q = 0; q < 4; q++) acc[mi][ni][q] = 0.f;

        const int lrow = lane & 15;
        const int lcb  = (lane >> 4) * 16;

        hy_load_tiles(Ahi, Whi, m0, n0, 0, sb, sb + ATILE_B, t);
        CP_COMMIT();

        for (int iter = 0; iter < T_NIT; iter++) {
            const int s = iter & 1;
            if (iter + 1 < T_NIT) {
                const int nit  = iter + 1;
                const int slab = nit >> 3;
                const int kc   = (nit & 7) * 64;
                const __nv_bfloat16* Ap = (slab == 1) ? Alo : Ahi;
                const __nv_bfloat16* Bp = (slab == 2) ? Wlo : Whi;
                hy_load_tiles(Ap, Bp, m0, n0, kc,
                              sb + (s^1)*STAGE_B, sb + (s^1)*STAGE_B + ATILE_B, t);
                CP_COMMIT();
                asm volatile("cp.async.wait_group 1;" ::: "memory");
            } else {
                CP_WAIT0();
            }
            BAR(2, 256);

            const uint32_t sa  = sb + s*STAGE_B;
            const uint32_t sbb = sa + ATILE_B;
#pragma unroll
            for (int kk = 0; kk < 4; kk++) {
                uint32_t a[4][4], bfr[2][4];
#pragma unroll
                for (int mi = 0; mi < 4; mi++) {
                    uint32_t off = (uint32_t)((wm + mi*16 + lrow)*128 + kk*32 + lcb);
                    ldsm_x4(a[mi][0], a[mi][1], a[mi][2], a[mi][3], sa + sw128(off));
                }
#pragma unroll
                for (int hh = 0; hh < 2; hh++) {
                    uint32_t off = (uint32_t)((wn + hh*16 + lrow)*128 + kk*32 + lcb);
                    ldsm_x4(bfr[hh][0], bfr[hh][1], bfr[hh][2], bfr[hh][3], sbb + sw128(off));
                }
#pragma unroll
                for (int mi = 0; mi < 4; mi++) {
                    mma_bf16(acc[mi][0], a[mi], bfr[0][0], bfr[0][2]);
                    mma_bf16(acc[mi][1], a[mi], bfr[0][1], bfr[0][3]);
                    mma_bf16(acc[mi][2], a[mi], bfr[1][0], bfr[1][2]);
                    mma_bf16(acc[mi][3], a[mi], bfr[1][1], bfr[1][3]);
                }
            }
            BAR(2, 256);
        }

        const int r  = lane >> 2;
        const int c2 = (lane & 3) * 2;
#pragma unroll
        for (int mi = 0; mi < 4; mi++)
#pragma unroll
            for (int ni = 0; ni < 4; ni++) {
                const int row = wm + mi*16 + r;
                const int col = wn + ni*8 + c2;
                *(float2*)&stag[row * 132 + col]       = make_float2(acc[mi][ni][0], acc[mi][ni][1]);
                *(float2*)&stag[(row + 8) * 132 + col] = make_float2(acc[mi][ni][2], acc[mi][ni][3]);
            }

        BAR(0, 512);
    }
}

__global__ __launch_bounds__(512)
void gemm_hybrid(const float* __restrict__ A, const float* __restrict__ W,
                 const __nv_bfloat16* __restrict__ Ahi, const __nv_bfloat16* __restrict__ Alo,
                 const __nv_bfloat16* __restrict__ Whi, const __nv_bfloat16* __restrict__ Wlo,
                 float* __restrict__ C)
{
    extern __shared__ char dsm[];
    __shared__ float As[16][132];
    __shared__ float Bs[16][132];
    gemm_tile(A, W, Ahi, Alo, Whi, Wlo, C, nullptr, nullptr,
              blockIdx.y * 128, blockIdx.x * 128, dsm, As, Bs);
}

__global__ __launch_bounds__(512)
void gemm_hybrid_qkv(
    const float* __restrict__ q, const float* __restrict__ k, const float* __restrict__ v,
    const float* __restrict__ wq, const float* __restrict__ wk, const float* __restrict__ wv,
    const __nv_bfloat16* qh, const __nv_bfloat16* ql,
    const __nv_bfloat16* kh, const __nv_bfloat16* kl,
    const __nv_bfloat16* vh, const __nv_bfloat16* vl,
    const __nv_bfloat16* wqh, const __nv_bfloat16* wql,
    const __nv_bfloat16* wkh, const __nv_bfloat16* wkl,
    const __nv_bfloat16* wvh, const __nv_bfloat16* wvl,
    float* Qb, float* Kb, float* Vb,
    __nv_bfloat16* pqh, __nv_bfloat16* pql,
    __nv_bfloat16* pkh, __nv_bfloat16* pkl)
{
    extern __shared__ char dsm[];
    __shared__ float As[16][132];
    __shared__ float Bs[16][132];
    const int z = blockIdx.z;
    const float* A = (z == 0) ? q : (z == 1) ? k : v;
    const float* W = (z == 0) ? wq : (z == 1) ? wk : wv;
    const __nv_bfloat16* Ahi = (z == 0) ? qh : (z == 1) ? kh : vh;
    const __nv_bfloat16* Alo = (z == 0) ? ql : (z == 1) ? kl : vl;
    const __nv_bfloat16* Whi = (z == 0) ? wqh : (z == 1) ? wkh : wvh;
    const __nv_bfloat16* Wlo = (z == 0) ? wql : (z == 1) ? wkl : wvl;
    float* C = (z == 0) ? Qb : (z == 1) ? Kb : Vb;
    __nv_bfloat16* Chi = (z == 0) ? pqh : (z == 1) ? pkh : nullptr;
    __nv_bfloat16* Clo = (z == 0) ? pql : (z == 1) ? pkl : nullptr;
    gemm_tile(A, W, Ahi, Alo, Whi, Wlo, C, Chi, Clo,
              blockIdx.y * 128, blockIdx.x * 128, dsm, As, Bs);
}

// ---------------------------------------------------------------------------
// Fast 2^y (y <= 0), FMA-pipe only.
// ---------------------------------------------------------------------------
__device__ __forceinline__ float fexp2(float y)
{
    y = fmaxf(y, -126.f);
    float n = floorf(y);
    float f = y - n;
    float p = fmaf(f, 0.0013333558f, 0.0096181291f);
    p = fmaf(f, p, 0.0555041087f);
    p = fmaf(f, p, 0.2402265069f);
    p = fmaf(f, p, 0.6931471806f);
    p = fmaf(f, p, 1.0f);
    return __int_as_float(__float_as_int(p) + (((int)n) << 23));
}
#define EXP_C 0.18033688011112042f   // log2(e)/sqrt(64)

// ---------------------------------------------------------------------------
// Warp-specialized flash attention — exact R10 ordering (measured 462us):
// tensor group: MMA -> arrive full -> wait free/load next/wait cp.
// ---------------------------------------------------------------------------
#define FL_QH 0
#define FL_QL 16384
#define FL_K  32768
#define FL_V  65536
#define FL_S  100352
#define FL_SMEM 169984

__global__ __launch_bounds__(512, 1)
void flash_ws(const __nv_bfloat16* __restrict__ Qh, const __nv_bfloat16* __restrict__ Ql,
              const __nv_bfloat16* __restrict__ Kh, const __nv_bfloat16* __restrict__ Kl,
              const float* __restrict__ V, float* __restrict__ O,
              __nv_bfloat16* __restrict__ Ohi, __nv_bfloat16* __restrict__ Olo)
{
    extern __shared__ char smc[];
    const uint32_t sb = smem_u32(smc);
    float* smf = (float*)smc;
    const int tid = threadIdx.x;
    const int wid = tid >> 5;
    const int lane = tid & 31;

    const int q0 = ((S_/128) - 1 - (int)blockIdx.x) * 128;
    const int h  = blockIdx.y;
    const int bz = blockIdx.z;
    const size_t base = (size_t)(bz * S_) * E_ + h * 64;
    const int T = q0 / 64 + 2;

    if (wid < 8) {
        // =================== TENSOR GROUP (score producer) ==================
        const int t2 = tid;   // 0..255
        for (int i = t2; i < 1024; i += 256) {
            int r = i >> 3, c = (i & 7) * 16;
            uint32_t sw = sw128((uint32_t)(r*128 + c));
            cp16(sb + FL_QH + sw, (const char*)(Qh + base + (size_t)(q0 + r)*E_) + c);
            cp16(sb + FL_QL + sw, (const char*)(Ql + base + (size_t)(q0 + r)*E_) + c);
        }
        for (int i = t2; i < 512; i += 256) {
            int r = i >> 3, c = (i & 7) * 16;
            uint32_t sw = sw128((uint32_t)(r*128 + c));
            cp16(sb + FL_K + sw,        (const char*)(Kh + base + (size_t)r*E_) + c);
            cp16(sb + FL_K + 8192 + sw, (const char*)(Kl + base + (size_t)r*E_) + c);
        }
        for (int i = t2; i < 1024; i += 256) {
            int r = i >> 4, c = (i & 15) * 16;
            cp16(sb + FL_V + (uint32_t)(r*272 + c),
                 (const char*)(V + base + (size_t)r*E_) + c);
        }
        CP_COMMIT();
        CP_WAIT0();
        BAR(5, 256);

        const int wm = (wid & 1) * 64;
        const int wn = (wid >> 1) * 16;
        const int lrow = lane & 15;
        const int lcb  = (lane >> 4) * 16;
        const int r4 = lane >> 2;
        const int c2 = (lane & 3) * 2;

        for (int t = 0; t < T; t++) {
            const int bb = t & 1;
            float acc[4][2][4];
#pragma unroll
            for (int mi = 0; mi < 4; mi++)
#pragma unroll
                for (int ni = 0; ni < 2; ni++)
#pragma unroll
                    for (int q = 0; q < 4; q++) acc[mi][ni][q] = 0.f;

#pragma unroll
            for (int slab = 0; slab < 3; slab++) {
                const uint32_t aB = sb + ((slab == 1) ? FL_QL : FL_QH);
                const uint32_t bB = sb + FL_K + bb*16384 + ((slab == 2) ? 8192 : 0);
#pragma unroll
                for (int kk = 0; kk < 4; kk++) {
                    uint32_t a[4][4], bf[4];
#pragma unroll
                    for (int mi = 0; mi < 4; mi++) {
                        uint32_t off = (uint32_t)((wm + mi*16 + lrow)*128 + kk*32 + lcb);
                        ldsm_x4(a[mi][0], a[mi][1], a[mi][2], a[mi][3], aB + sw128(off));
                    }
                    {
                        uint32_t off = (uint32_t)((wn + lrow)*128 + kk*32 + lcb);
                        ldsm_x4(bf[0], bf[1], bf[2], bf[3], bB + sw128(off));
                    }
#pragma unroll
                    for (int mi = 0; mi < 4; mi++) {
                        mma_bf16(acc[mi][0], a[mi], bf[0], bf[2]);
                        mma_bf16(acc[mi][1], a[mi], bf[1], bf[3]);
                    }
                }
            }
            // store raw scores to S[bb]
            float* st = smf + (FL_S + bb*34816) / 4;
#pragma unroll
            for (int mi = 0; mi < 4; mi++)
#pragma unroll
                for (int ni = 0; ni < 2; ni++) {
                    const int row = wm + mi*16 + r4;
                    const int col = wn + ni*8 + c2;
                    *(float2*)&st[row * 68 + col]       = make_float2(acc[mi][ni][0], acc[mi][ni][1]);
                    *(float2*)&st[(row + 8) * 68 + col] = make_float2(acc[mi][ni][2], acc[mi][ni][3]);
                }
            MEMBAR_CTA();
            BAR_ARRIVE(1 + bb, 512);           // S[bb] full

            if (t + 1 < T) {
                const int nb = bb ^ 1;
                if (t >= 1) BAR(3 + nb, 512);  // wait stage nb free
                const int k0n = (t + 1) * 64;
                for (int i = t2; i < 512; i += 256) {
                    int r = i >> 3, c = (i & 7) * 16;
                    uint32_t sw = sw128((uint32_t)(r*128 + c));
                    cp16(sb + FL_K + nb*16384 + sw,
                         (const char*)(Kh + base + (size_t)(k0n + r)*E_) + c);
                    cp16(sb + FL_K + nb*16384 + 8192 + sw,
                         (const char*)(Kl + base + (size_t)(k0n + r)*E_) + c);
                }
                for (int i = t2; i < 1024; i += 256) {
                    int r = i >> 4, c = (i & 15) * 16;
                    cp16(sb + FL_V + nb*17408 + (uint32_t)(r*272 + c),
                         (const char*)(V + base + (size_t)(k0n + r)*E_) + c);
                }
                CP_COMMIT();
                CP_WAIT0();
                BAR(5, 256);
            }
        }
    } else {
        // =================== FFMA GROUP (softmax + PV) ======================
        const int t2 = tid - 256;
        const int tx = t2 & 15;
        const int ty = t2 >> 4;
        const int tm = ty * 8;
        const int tn = tx * 4;

        float o[8][4];
        float m_i[8], l_i[8];
#pragma unroll
        for (int i = 0; i < 8; i++) {
            m_i[i] = -1e30f; l_i[i] = 0.f;
#pragma unroll
            for (int j = 0; j < 4; j++) o[i][j] = 0.f;
        }

        for (int t = 0; t < T; t++) {
            const int bb = t & 1;
            const int k0 = t * 64;
            BAR(1 + bb, 512);                 // wait S[bb] full
            float* SS = smf + (FL_S + bb*34816) / 4;
            float* SV = smf + (FL_V + bb*17408) / 4;

            float s[8][4];
#pragma unroll
            for (int i = 0; i < 8; i++) {
                float4 sv = *(const float4*)&SS[(tm + i) * 68 + tn];
                s[i][0] = sv.x; s[i][1] = sv.y; s[i][2] = sv.z; s[i][3] = sv.w;
            }

            if (k0 >= q0) {
#pragma unroll
                for (int i = 0; i < 8; i++)
#pragma unroll
                    for (int j = 0; j < 4; j++)
                        if (k0 + tn + j > q0 + tm + i) s[i][j] = -1e30f;
            }

#pragma unroll
            for (int i = 0; i < 8; i++) {
                float rm = fmaxf(fmaxf(s[i][0], s[i][1]), fmaxf(s[i][2], s[i][3]));
#pragma unroll
                for (int off = 8; off >= 1; off >>= 1)
                    rm = fmaxf(rm, __shfl_xor_sync(0xffffffffu, rm, off));
                float mnew = fmaxf(m_i[i], rm);
                float scal = fexp2((m_i[i] - mnew) * EXP_C);
                float sum = 0.f;
#pragma unroll
                for (int j = 0; j < 4; j++) {
                    s[i][j] = fexp2((s[i][j] - mnew) * EXP_C);
                    sum += s[i][j];
                }
#pragma unroll
                for (int off = 8; off >= 1; off >>= 1)
                    sum += __shfl_xor_sync(0xffffffffu, sum, off);
                l_i[i] = l_i[i] * scal + sum;
                m_i[i] = mnew;
#pragma unroll
                for (int j = 0; j < 4; j++) o[i][j] *= scal;
            }

            // write P in place
#pragma unroll
            for (int i = 0; i < 8; i++)
                *(float4*)&SS[(tm + i) * 68 + tn] =
                    make_float4(s[i][0], s[i][1], s[i][2], s[i][3]);
            BAR(6, 256);

            // PV
#pragma unroll 4
            for (int k4 = 0; k4 < 64; k4 += 4) {
                float4 v0 = *(const float4*)&SV[(k4 + 0) * 68 + tn];
                float4 v1 = *(const float4*)&SV[(k4 + 1) * 68 + tn];
                float4 v2 = *(const float4*)&SV[(k4 + 2) * 68 + tn];
                float4 v3 = *(const float4*)&SV[(k4 + 3) * 68 + tn];
#pragma unroll
                for (int i = 0; i < 8; i++) {
                    float4 pr = *(const float4*)&SS[(tm + i) * 68 + k4];
                    o[i][0] = fmaf(pr.x, v0.x, o[i][0]);
                    o[i][1] = fmaf(pr.x, v0.y, o[i][1]);
                    o[i][2] = fmaf(pr.x, v0.z, o[i][2]);
                    o[i][3] = fmaf(pr.x, v0.w, o[i][3]);
                    o[i][0] = fmaf(pr.y, v1.x, o[i][0]);
                    o[i][1] = fmaf(pr.y, v1.y, o[i][1]);
                    o[i][2] = fmaf(pr.y, v1.z, o[i][2]);
                    o[i][3] = fmaf(pr.y, v1.w, o[i][3]);
                    o[i][0] = fmaf(pr.z, v2.x, o[i][0]);
                    o[i][1] = fmaf(pr.z, v2.y, o[i][1]);
                    o[i][2] = fmaf(pr.z, v2.z, o[i][2]);
                    o[i][3] = fmaf(pr.z, v2.w, o[i][3]);
                    o[i][0] = fmaf(pr.w, v3.x, o[i][0]);
                    o[i][1] = fmaf(pr.w, v3.y, o[i][1]);
                    o[i][2] = fmaf(pr.w, v3.z, o[i][2]);
                    o[i][3] = fmaf(pr.w, v3.w, o[i][3]);
                }
            }
            BAR_ARRIVE(3 + bb, 512);          // stage bb free
        }

        // epilogue: normalize + fp32 + bf16 hi/lo split
#pragma unroll
        for (int i = 0; i < 8; i++) {
            float inv = 1.f / l_i[i];
            float r0 = o[i][0] * inv, r1 = o[i][1] * inv;
            float r2 = o[i][2] * inv, r3 = o[i][3] * inv;
            size_t idx = base + (size_t)(q0 + tm + i) * E_ + tn;
            *(float4*)&O[idx] = make_float4(r0, r1, r2, r3);
            __nv_bfloat16 h0 = __float2bfloat16(r0);
            __nv_bfloat16 h1 = __float2bfloat16(r1);
            __nv_bfloat16 h2 = __float2bfloat16(r2);
            __nv_bfloat16 h3 = __float2bfloat16(r3);
            __nv_bfloat162 ph0; ph0.x = h0; ph0.y = h1;
            __nv_bfloat162 ph1; ph1.x = h2; ph1.y = h3;
            __nv_bfloat162 pl0;
            pl0.x = __float2bfloat16(r0 - __bfloat162float(h0));
            pl0.y = __float2bfloat16(r1 - __bfloat162float(h1));
            __nv_bfloat162 pl1;
            pl1.x = __float2bfloat16(r2 - __bfloat162float(h2));
            pl1.y = __float2bfloat16(r3 - __bfloat162float(h3));
            *(__nv_bfloat162*)&Ohi[idx]     = ph0;
            *(__nv_bfloat162*)&Ohi[idx + 2] = ph1;
            *(__nv_bfloat162*)&Olo[idx]     = pl0;
            *(__nv_bfloat162*)&Olo[idx + 2] = pl1;
        }
    }
}

// ---------------------------------------------------------------------------
extern "C" void kernel_launch(void* const* d_in, const int* in_sizes, int n_in,
                              void* d_out, int out_size)
{
    const float* query = (const float*)d_in[0];
    const float* key   = (const float*)d_in[1];
    const float* value = (const float*)d_in[2];
    // d_in[3] = mask (causal, structural) — unused
    const float* w_q = (const float*)d_in[4];
    const float* w_k = (const float*)d_in[5];
    const float* w_v = (const float*)d_in[6];
    const float* w_o = (const float*)d_in[7];
    float* out = (float*)d_out;

    float *Qb, *Kb, *Vb, *Ab;
    cudaGetSymbolAddress((void**)&Qb, g_Q);
    cudaGetSymbolAddress((void**)&Kb, g_K);
    cudaGetSymbolAddress((void**)&Vb, g_V);
    cudaGetSymbolAddress((void**)&Ab, g_A);
    __nv_bfloat16 *qh, *ql, *kh, *kl, *vh, *vl, *ah, *al, *wh, *wl;
    __nv_bfloat16 *pqh, *pql, *pkh, *pkl;
    cudaGetSymbolAddress((void**)&qh, g_qhi);
    cudaGetSymbolAddress((void**)&ql, g_qlo);
    cudaGetSymbolAddress((void**)&kh, g_khi);
    cudaGetSymbolAddress((void**)&kl, g_klo);
    cudaGetSymbolAddress((void**)&vh, g_vhi);
    cudaGetSymbolAddress((void**)&vl, g_vlo);
    cudaGetSymbolAddress((void**)&ah, g_ahi);
    cudaGetSymbolAddress((void**)&al, g_alo);
    cudaGetSymbolAddress((void**)&wh, g_whi);
    cudaGetSymbolAddress((void**)&wl, g_wlo);
    cudaGetSymbolAddress((void**)&pqh, g_pqh);
    cudaGetSymbolAddress((void**)&pql, g_pql);
    cudaGetSymbolAddress((void**)&pkh, g_pkh);
    cudaGetSymbolAddress((void**)&pkl, g_pkl);
    const int WSZ = E_*E_;

    cudaFuncSetAttribute(flash_ws,
                         cudaFuncAttributeMaxDynamicSharedMemorySize, FL_SMEM);
    cudaFuncSetAttribute(gemm_hybrid,
                         cudaFuncAttributeMaxDynamicSharedMemorySize, HY_DSMEM);
    cudaFuncSetAttribute(gemm_hybrid_qkv,
                         cudaFuncAttributeMaxDynamicSharedMemorySize, HY_DSMEM);

    const int actN4 = M_ * E_ / 4;
    const int wN4   = E_ * E_ / 4;

    split3<<<dim3(actN4/256, 3), 256>>>(query, key, value,
                                        qh, ql, kh, kl, vh, vl, actN4);
    split4<<<dim3(wN4/256, 4), 256>>>(w_q, w_k, w_v, w_o,
                                      wh + 0*WSZ, wl + 0*WSZ, wh + 1*WSZ, wl + 1*WSZ,
                                      wh + 2*WSZ, wl + 2*WSZ, wh + 3*WSZ, wl + 3*WSZ, wN4);

    gemm_hybrid_qkv<<<dim3(E_/128, M_/128, 3), 512, HY_DSMEM>>>(
        query, key, value, w_q, w_k, w_v,
        qh, ql, kh, kl, vh, vl,
        wh + 0*WSZ, wl + 0*WSZ, wh + 1*WSZ, wl + 1*WSZ, wh + 2*WSZ, wl + 2*WSZ,
        Qb, Kb, Vb, pqh, pql, pkh, pkl);

    flash_ws<<<dim3(S_/128, H_, B_), 512, FL_SMEM>>>(
        pqh, pql, pkh, pkl, Vb, Ab, ah, al);

    gemm_hybrid<<<dim3(E_/128, M_/128), 512, HY_DSMEM>>>(
        Ab, w_o, ah, al, wh + 3*WSZ, wl + 3*WSZ, out);
}

// round 16
// speedup vs baseline: 1.0021x; 1.0021x over previous
#include <cuda_runtime.h>
#include <cuda_bf16.h>
#include <cstdint>

#define B_ 2
#define S_ 2048
#define E_ 1024
#define H_ 16
#define D_ 64
#define M_ (B_*S_)   // 4096 rows

// Scratch (device globals; no allocation)
__device__ float g_Q[M_*E_];
__device__ float g_K[M_*E_];
__device__ float g_V[M_*E_];
__device__ float g_A[M_*E_];
__device__ __align__(16) __nv_bfloat16 g_qhi[M_*E_];
__device__ __align__(16) __nv_bfloat16 g_qlo[M_*E_];
__device__ __align__(16) __nv_bfloat16 g_khi[M_*E_];
__device__ __align__(16) __nv_bfloat16 g_klo[M_*E_];
__device__ __align__(16) __nv_bfloat16 g_vhi[M_*E_];
__device__ __align__(16) __nv_bfloat16 g_vlo[M_*E_];
__device__ __align__(16) __nv_bfloat16 g_ahi[M_*E_];
__device__ __align__(16) __nv_bfloat16 g_alo[M_*E_];
__device__ __align__(16) __nv_bfloat16 g_whi[4][E_*E_];
__device__ __align__(16) __nv_bfloat16 g_wlo[4][E_*E_];
// splits of the PROJECTED Q and K (written by QKV GEMM epilogue)
__device__ __align__(16) __nv_bfloat16 g_pqh[M_*E_];
__device__ __align__(16) __nv_bfloat16 g_pql[M_*E_];
__device__ __align__(16) __nv_bfloat16 g_pkh[M_*E_];
__device__ __align__(16) __nv_bfloat16 g_pkl[M_*E_];

// ---------------- PTX helpers ----------------------------------------------
__device__ __forceinline__ uint32_t smem_u32(const void* p) {
    uint32_t a;
    asm("{ .reg .u64 t; cvta.to.shared.u64 t, %1; cvt.u32.u64 %0, t; }"
        : "=r"(a) : "l"(p));
    return a;
}
__device__ __forceinline__ void cp16(uint32_t dst, const void* src) {
    asm volatile("cp.async.cg.shared.global [%0], [%1], 16;" :: "r"(dst), "l"(src));
}
#define CP_COMMIT() asm volatile("cp.async.commit_group;" ::: "memory")
#define CP_WAIT0()  asm volatile("cp.async.wait_group 0;" ::: "memory")
#define BAR(id, cnt) asm volatile("bar.sync %0, %1;" :: "r"(id), "r"(cnt) : "memory")
#define BAR_ARRIVE(id, cnt) asm volatile("bar.arrive %0, %1;" :: "r"(id), "r"(cnt) : "memory")

__device__ __forceinline__ void ldsm_x4(uint32_t& r0, uint32_t& r1,
                                        uint32_t& r2, uint32_t& r3, uint32_t addr) {
    asm volatile("ldmatrix.sync.aligned.m8n8.x4.shared.b16 {%0,%1,%2,%3}, [%4];"
                 : "=r"(r0), "=r"(r1), "=r"(r2), "=r"(r3) : "r"(addr));
}
__device__ __forceinline__ void mma_bf16(float* d, const uint32_t* a,
                                         uint32_t b0, uint32_t b1) {
    asm volatile(
        "mma.sync.aligned.m16n8k16.row.col.f32.bf16.bf16.f32 "
        "{%0,%1,%2,%3}, {%4,%5,%6,%7}, {%8,%9}, {%0,%1,%2,%3};"
        : "+f"(d[0]), "+f"(d[1]), "+f"(d[2]), "+f"(d[3])
        : "r"(a[0]), "r"(a[1]), "r"(a[2]), "r"(a[3]), "r"(b0), "r"(b1));
}
__device__ __forceinline__ uint32_t sw128(uint32_t off) {
    return off ^ ((off >> 3) & 0x70);
}

// ---------------------------------------------------------------------------
// Batched splits: fp32 -> (hi, lo) bf16. One launch for all 7 tensors.
// ---------------------------------------------------------------------------
__device__ __forceinline__ void split_one(const float* __restrict__ x,
                                          __nv_bfloat16* __restrict__ hi,
                                          __nv_bfloat16* __restrict__ lo, int i)
{
    float4 v = ((const float4*)x)[i];
    __nv_bfloat16 h0 = __float2bfloat16(v.x);
    __nv_bfloat16 h1 = __float2bfloat16(v.y);
    __nv_bfloat16 h2 = __float2bfloat16(v.z);
    __nv_bfloat16 h3 = __float2bfloat16(v.w);
    __nv_bfloat16 l0 = __float2bfloat16(v.x - __bfloat162float(h0));
    __nv_bfloat16 l1 = __float2bfloat16(v.y - __bfloat162float(h1));
    __nv_bfloat16 l2 = __float2bfloat16(v.z - __bfloat162float(h2));
    __nv_bfloat16 l3 = __float2bfloat16(v.w - __bfloat162float(h3));
    __nv_bfloat162 ph0; ph0.x = h0; ph0.y = h1;
    __nv_bfloat162 ph1; ph1.x = h2; ph1.y = h3;
    __nv_bfloat162 pl0; pl0.x = l0; pl0.y = l1;
    __nv_bfloat162 pl1; pl1.x = l2; pl1.y = l3;
    ((__nv_bfloat162*)hi)[i*2]   = ph0;
    ((__nv_bfloat162*)hi)[i*2+1] = ph1;
    ((__nv_bfloat162*)lo)[i*2]   = pl0;
    ((__nv_bfloat162*)lo)[i*2+1] = pl1;
}

__global__ __launch_bounds__(256)
void split7(const float* __restrict__ q, const float* __restrict__ k,
            const float* __restrict__ v,
            const float* __restrict__ w0, const float* __restrict__ w1,
            const float* __restrict__ w2, const float* __restrict__ w3,
            __nv_bfloat16* qh, __nv_bfloat16* ql, __nv_bfloat16* kh, __nv_bfloat16* kl,
            __nv_bfloat16* vh, __nv_bfloat16* vl,
            __nv_bfloat16* h0, __nv_bfloat16* l0, __nv_bfloat16* h1, __nv_bfloat16* l1,
            __nv_bfloat16* h2, __nv_bfloat16* l2, __nv_bfloat16* h3, __nv_bfloat16* l3,
            int n4act, int n4w)
{
    int i = blockIdx.x * blockDim.x + threadIdx.x;
    int z = blockIdx.y;
    const int n4 = (z < 3) ? n4act : n4w;
    if (i >= n4) return;
    const float* x;
    __nv_bfloat16 *hi, *lo;
    switch (z) {
        case 0: x = q;  hi = qh; lo = ql; break;
        case 1: x = k;  hi = kh; lo = kl; break;
        case 2: x = v;  hi = vh; lo = vl; break;
        case 3: x = w0; hi = h0; lo = l0; break;
        case 4: x = w1; hi = h1; lo = l1; break;
        case 5: x = w2; hi = h2; lo = l2; break;
        default: x = w3; hi = h3; lo = l3; break;
    }
    split_one(x, hi, lo, i);
}

// ---------------------------------------------------------------------------
// HYBRID GEMM tile body (128x128): warps 0-7 FFMA K[512,1024) with register
// software pipeline + DOUBLE-BUFFERED smem tiles (one barrier per chunk);
// warps 8-15 HMMA 3-slab bf16 K[0,512).
// ---------------------------------------------------------------------------
#define KF0 512
#define T_NIT 24
#define ATILE_B (128*128)
#define STAGE_B (2*ATILE_B)
#define STAG_F  (128*132)
#define HY_DSMEM (STAG_F*4)

__device__ __forceinline__ void hy_load_tiles(
    const __nv_bfloat16* __restrict__ Ap, const __nv_bfloat16* __restrict__ Bp,
    int m0, int n0, int kc, uint32_t sa, uint32_t sbb, int t)
{
#pragma unroll
    for (int i = 0; i < 4; i++) {
        int cidx = t + i*256;
        int row = cidx >> 3;
        int cb  = (cidx & 7) * 16;
        uint32_t sw = sw128((uint32_t)(row*128 + cb));
        cp16(sa  + sw, (const char*)(Ap + (size_t)(m0+row)*E_ + kc) + cb);
        cp16(sbb + sw, (const char*)(Bp + (size_t)(n0+row)*E_ + kc) + cb);
    }
}

__device__ __forceinline__ void gemm_tile(
    const float* __restrict__ A, const float* __restrict__ W,
    const __nv_bfloat16* __restrict__ Ahi, const __nv_bfloat16* __restrict__ Alo,
    const __nv_bfloat16* __restrict__ Whi, const __nv_bfloat16* __restrict__ Wlo,
    float* __restrict__ C, __nv_bfloat16* Chi, __nv_bfloat16* Clo,
    int m0, int n0, char* dsm, float (*As)[16][132], float (*Bs)[16][132])
{
    float* stag = (float*)dsm;
    const uint32_t sb = smem_u32(dsm);
    const int tid = threadIdx.x;
    const int wid = tid >> 5;
    const int lane = tid & 31;

    if (wid < 8) {
        const int t  = tid;
        const int tx = t & 15;
        const int ty = t >> 4;
        const int tm = ty * 8;
        const int tn = tx * 8;
        const int lr = t >> 2;
        const int lk = (t & 3) * 4;

        float acc[8][8];
#pragma unroll
        for (int i = 0; i < 8; i++)
#pragma unroll
            for (int j = 0; j < 8; j++) acc[i][j] = 0.f;

        const float* Ap0 = &A[(size_t)(m0 + lr) * E_];
        const float* Ap1 = &A[(size_t)(m0 + lr + 64) * E_];
        const float* Bp0 = &W[(size_t)(n0 + lr) * E_];
        const float* Bp1 = &W[(size_t)(n0 + lr + 64) * E_];

        // prologue prefetch (chunk 0)
        float4 pa0 = *(const float4*)(Ap0 + KF0 + lk);
        float4 pa1 = *(const float4*)(Ap1 + KF0 + lk);
        float4 pb0 = *(const float4*)(Bp0 + KF0 + lk);
        float4 pb1 = *(const float4*)(Bp1 + KF0 + lk);

        for (int k0 = KF0; k0 < E_; k0 += 16) {
            const int bsel = ((k0 - KF0) >> 4) & 1;
            // stage current chunk from registers into buffer bsel
            As[bsel][lk + 0][lr] = pa0.x; As[bsel][lk + 1][lr] = pa0.y;
            As[bsel][lk + 2][lr] = pa0.z; As[bsel][lk + 3][lr] = pa0.w;
            As[bsel][lk + 0][lr + 64] = pa1.x; As[bsel][lk + 1][lr + 64] = pa1.y;
            As[bsel][lk + 2][lr + 64] = pa1.z; As[bsel][lk + 3][lr + 64] = pa1.w;
            Bs[bsel][lk + 0][lr] = pb0.x; Bs[bsel][lk + 1][lr] = pb0.y;
            Bs[bsel][lk + 2][lr] = pb0.z; Bs[bsel][lk + 3][lr] = pb0.w;
            Bs[bsel][lk + 0][lr + 64] = pb1.x; Bs[bsel][lk + 1][lr + 64] = pb1.y;
            Bs[bsel][lk + 2][lr + 64] = pb1.z; Bs[bsel][lk + 3][lr + 64] = pb1.w;
            // prefetch next chunk (latency hidden under barrier + compute)
            if (k0 + 16 < E_) {
                pa0 = *(const float4*)(Ap0 + k0 + 16 + lk);
                pa1 = *(const float4*)(Ap1 + k0 + 16 + lk);
                pb0 = *(const float4*)(Bp0 + k0 + 16 + lk);
                pb1 = *(const float4*)(Bp1 + k0 + 16 + lk);
            }
            BAR(1, 256);   // single barrier: stores of chunk k visible; implies
                           // compute(k-2) done, so next iter's buffer is free
#pragma unroll
            for (int kk = 0; kk < 16; kk++) {
                float a[8], b[8];
                float4 tt;
                tt = *(const float4*)&As[bsel][kk][tm];     a[0]=tt.x; a[1]=tt.y; a[2]=tt.z; a[3]=tt.w;
                tt = *(const float4*)&As[bsel][kk][tm + 4]; a[4]=tt.x; a[5]=tt.y; a[6]=tt.z; a[7]=tt.w;
                tt = *(const float4*)&Bs[bsel][kk][tn];     b[0]=tt.x; b[1]=tt.y; b[2]=tt.z; b[3]=tt.w;
                tt = *(const float4*)&Bs[bsel][kk][tn + 4]; b[4]=tt.x; b[5]=tt.y; b[6]=tt.z; b[7]=tt.w;
#pragma unroll
                for (int i = 0; i < 8; i++)
#pragma unroll
                    for (int j = 0; j < 8; j++)
                        acc[i][j] = fmaf(a[i], b[j], acc[i][j]);
            }
        }

        BAR(0, 512);

#pragma unroll
        for (int i = 0; i < 8; i++) {
            const float* sp = &stag[(tm + i) * 132 + tn];
            float4 s0 = *(const float4*)&sp[0];
            float4 s1 = *(const float4*)&sp[4];
            float r0 = acc[i][0] + s0.x, r1 = acc[i][1] + s0.y;
            float r2 = acc[i][2] + s0.z, r3 = acc[i][3] + s0.w;
            float r4 = acc[i][4] + s1.x, r5 = acc[i][5] + s1.y;
            float r6 = acc[i][6] + s1.z, r7 = acc[i][7] + s1.w;
            size_t idx = (size_t)(m0 + tm + i) * E_ + n0 + tn;
            *(float4*)&C[idx]     = make_float4(r0, r1, r2, r3);
            *(float4*)&C[idx + 4] = make_float4(r4, r5, r6, r7);
            if (Chi) {
                float rv[8] = {r0, r1, r2, r3, r4, r5, r6, r7};
#pragma unroll
                for (int p = 0; p < 4; p++) {
                    __nv_bfloat16 h0 = __float2bfloat16(rv[p*2]);
                    __nv_bfloat16 h1 = __float2bfloat16(rv[p*2+1]);
                    __nv_bfloat162 ph; ph.x = h0; ph.y = h1;
                    __nv_bfloat162 pl;
                    pl.x = __float2bfloat16(rv[p*2]   - __bfloat162float(h0));
                    pl.y = __float2bfloat16(rv[p*2+1] - __bfloat162float(h1));
                    *(__nv_bfloat162*)&Chi[idx + p*2] = ph;
                    *(__nv_bfloat162*)&Clo[idx + p*2] = pl;
                }
            }
        }
    } else {
        const int t = tid - 256;
        const int wt = wid - 8;
        const int wm = (wt & 1) * 64;
        const int wn = (wt >> 1) * 32;

        float acc[4][4][4];
#pragma unroll
        for (int mi = 0; mi < 4; mi++)
#pragma unroll
            for (int ni = 0; ni < 4; ni++)
#pragma unroll
                for (int q = 0; q < 4; q++) acc[mi][ni][q] = 0.f;

        const int lrow = lane & 15;
        const int lcb  = (lane >> 4) * 16;

        hy_load_tiles(Ahi, Whi, m0, n0, 0, sb, sb + ATILE_B, t);
        CP_COMMIT();

        for (int iter = 0; iter < T_NIT; iter++) {
            const int s = iter & 1;
            if (iter + 1 < T_NIT) {
                const int nit  = iter + 1;
                const int slab = nit >> 3;
                const int kc   = (nit & 7) * 64;
                const __nv_bfloat16* Ap = (slab == 1) ? Alo : Ahi;
                const __nv_bfloat16* Bp = (slab == 2) ? Wlo : Whi;
                hy_load_tiles(Ap, Bp, m0, n0, kc,
                              sb + (s^1)*STAGE_B, sb + (s^1)*STAGE_B + ATILE_B, t);
                CP_COMMIT();
                asm volatile("cp.async.wait_group 1;" ::: "memory");
            } else {
                CP_WAIT0();
            }
            BAR(2, 256);

            const uint32_t sa  = sb + s*STAGE_B;
            const uint32_t sbb = sa + ATILE_B;
#pragma unroll
            for (int kk = 0; kk < 4; kk++) {
                uint32_t a[4][4], bfr[2][4];
#pragma unroll
                for (int mi = 0; mi < 4; mi++) {
                    uint32_t off = (uint32_t)((wm + mi*16 + lrow)*128 + kk*32 + lcb);
                    ldsm_x4(a[mi][0], a[mi][1], a[mi][2], a[mi][3], sa + sw128(off));
                }
#pragma unroll
                for (int hh = 0; hh < 2; hh++) {
                    uint32_t off = (uint32_t)((wn + hh*16 + lrow)*128 + kk*32 + lcb);
                    ldsm_x4(bfr[hh][0], bfr[hh][1], bfr[hh][2], bfr[hh][3], sbb + sw128(off));
                }
#pragma unroll
                for (int mi = 0; mi < 4; mi++) {
                    mma_bf16(acc[mi][0], a[mi], bfr[0][0], bfr[0][2]);
                    mma_bf16(acc[mi][1], a[mi], bfr[0][1], bfr[0][3]);
                    mma_bf16(acc[mi][2], a[mi], bfr[1][0], bfr[1][2]);
                    mma_bf16(acc[mi][3], a[mi], bfr[1][1], bfr[1][3]);
                }
            }
            BAR(2, 256);
        }

        const int r  = lane >> 2;
        const int c2 = (lane & 3) * 2;
#pragma unroll
        for (int mi = 0; mi < 4; mi++)
#pragma unroll
            for (int ni = 0; ni < 4; ni++) {
                const int row = wm + mi*16 + r;
                const int col = wn + ni*8 + c2;
                *(float2*)&stag[row * 132 + col]       = make_float2(acc[mi][ni][0], acc[mi][ni][1]);
                *(float2*)&stag[(row + 8) * 132 + col] = make_float2(acc[mi][ni][2], acc[mi][ni][3]);
            }

        BAR(0, 512);
    }
}

__global__ __launch_bounds__(512)
void gemm_hybrid(const float* __restrict__ A, const float* __restrict__ W,
                 const __nv_bfloat16* __restrict__ Ahi, const __nv_bfloat16* __restrict__ Alo,
                 const __nv_bfloat16* __restrict__ Whi, const __nv_bfloat16* __restrict__ Wlo,
                 float* __restrict__ C)
{
    extern __shared__ char dsm[];
    __shared__ float As[2][16][132];
    __shared__ float Bs[2][16][132];
    gemm_tile(A, W, Ahi, Alo, Whi, Wlo, C, nullptr, nullptr,
              blockIdx.y * 128, blockIdx.x * 128, dsm, As, Bs);
}

__global__ __launch_bounds__(512)
void gemm_hybrid_qkv(
    const float* __restrict__ q, const float* __restrict__ k, const float* __restrict__ v,
    const float* __restrict__ wq, const float* __restrict__ wk, const float* __restrict__ wv,
    const __nv_bfloat16* qh, const __nv_bfloat16* ql,
    const __nv_bfloat16* kh, const __nv_bfloat16* kl,
    const __nv_bfloat16* vh, const __nv_bfloat16* vl,
    const __nv_bfloat16* wqh, const __nv_bfloat16* wql,
    const __nv_bfloat16* wkh, const __nv_bfloat16* wkl,
    const __nv_bfloat16* wvh, const __nv_bfloat16* wvl,
    float* Qb, float* Kb, float* Vb,
    __nv_bfloat16* pqh, __nv_bfloat16* pql,
    __nv_bfloat16* pkh, __nv_bfloat16* pkl)
{
    extern __shared__ char dsm[];
    __shared__ float As[2][16][132];
    __shared__ float Bs[2][16][132];
    const int z = blockIdx.z;
    const float* A = (z == 0) ? q : (z == 1) ? k : v;
    const float* W = (z == 0) ? wq : (z == 1) ? wk : wv;
    const __nv_bfloat16* Ahi = (z == 0) ? qh : (z == 1) ? kh : vh;
    const __nv_bfloat16* Alo = (z == 0) ? ql : (z == 1) ? kl : vl;
    const __nv_bfloat16* Whi = (z == 0) ? wqh : (z == 1) ? wkh : wvh;
    const __nv_bfloat16* Wlo = (z == 0) ? wql : (z == 1) ? wkl : wvl;
    float* C = (z == 0) ? Qb : (z == 1) ? Kb : Vb;
    __nv_bfloat16* Chi = (z == 0) ? pqh : (z == 1) ? pkh : nullptr;
    __nv_bfloat16* Clo = (z == 0) ? pql : (z == 1) ? pkl : nullptr;
    gemm_tile(A, W, Ahi, Alo, Whi, Wlo, C, Chi, Clo,
              blockIdx.y * 128, blockIdx.x * 128, dsm, As, Bs);
}

// ---------------------------------------------------------------------------
// Fast 2^y (y <= 0), FMA-pipe only.
// ---------------------------------------------------------------------------
__device__ __forceinline__ float fexp2(float y)
{
    y = fmaxf(y, -126.f);
    float n = floorf(y);
    float f = y - n;
    float p = fmaf(f, 0.0013333558f, 0.0096181291f);
    p = fmaf(f, p, 0.0555041087f);
    p = fmaf(f, p, 0.2402265069f);
    p = fmaf(f, p, 0.6931471806f);
    p = fmaf(f, p, 1.0f);
    return __int_as_float(__float_as_int(p) + (((int)n) << 23));
}
#define EXP_C 0.18033688011112042f   // log2(e)/sqrt(64)

// ---------------------------------------------------------------------------
// Warp-specialized flash attention — R10 ordering; membar removed (BAR drains
// STS natively per B300 doc); FFMA-internal barrier -> __syncwarp (PV reads
// only own-warp P rows).
// ---------------------------------------------------------------------------
#define FL_QH 0
#define FL_QL 16384
#define FL_K  32768
#define FL_V  65536
#define FL_S  100352
#define FL_SMEM 169984

__global__ __launch_bounds__(512, 1)
void flash_ws(const __nv_bfloat16* __restrict__ Qh, const __nv_bfloat16* __restrict__ Ql,
              const __nv_bfloat16* __restrict__ Kh, const __nv_bfloat16* __restrict__ Kl,
              const float* __restrict__ V, float* __restrict__ O,
              __nv_bfloat16* __restrict__ Ohi, __nv_bfloat16* __restrict__ Olo)
{
    extern __shared__ char smc[];
    const uint32_t sb = smem_u32(smc);
    float* smf = (float*)smc;
    const int tid = threadIdx.x;
    const int wid = tid >> 5;
    const int lane = tid & 31;

    const int q0 = ((S_/128) - 1 - (int)blockIdx.x) * 128;
    const int h  = blockIdx.y;
    const int bz = blockIdx.z;
    const size_t base = (size_t)(bz * S_) * E_ + h * 64;
    const int T = q0 / 64 + 2;

    if (wid < 8) {
        // =================== TENSOR GROUP (score producer) ==================
        const int t2 = tid;   // 0..255
        for (int i = t2; i < 1024; i += 256) {
            int r = i >> 3, c = (i & 7) * 16;
            uint32_t sw = sw128((uint32_t)(r*128 + c));
            cp16(sb + FL_QH + sw, (const char*)(Qh + base + (size_t)(q0 + r)*E_) + c);
            cp16(sb + FL_QL + sw, (const char*)(Ql + base + (size_t)(q0 + r)*E_) + c);
        }
        for (int i = t2; i < 512; i += 256) {
            int r = i >> 3, c = (i & 7) * 16;
            uint32_t sw = sw128((uint32_t)(r*128 + c));
            cp16(sb + FL_K + sw,        (const char*)(Kh + base + (size_t)r*E_) + c);
            cp16(sb + FL_K + 8192 + sw, (const char*)(Kl + base + (size_t)r*E_) + c);
        }
        for (int i = t2; i < 1024; i += 256) {
            int r = i >> 4, c = (i & 15) * 16;
            cp16(sb + FL_V + (uint32_t)(r*272 + c),
                 (const char*)(V + base + (size_t)r*E_) + c);
        }
        CP_COMMIT();
        CP_WAIT0();
        BAR(5, 256);

        const int wm = (wid & 1) * 64;
        const int wn = (wid >> 1) * 16;
        const int lrow = lane & 15;
        const int lcb  = (lane >> 4) * 16;
        const int r4 = lane >> 2;
        const int c2 = (lane & 3) * 2;

        for (int t = 0; t < T; t++) {
            const int bb = t & 1;
            float acc[4][2][4];
#pragma unroll
            for (int mi = 0; mi < 4; mi++)
#pragma unroll
                for (int ni = 0; ni < 2; ni++)
#pragma unroll
                    for (int q = 0; q < 4; q++) acc[mi][ni][q] = 0.f;

#pragma unroll
            for (int slab = 0; slab < 3; slab++) {
                const uint32_t aB = sb + ((slab == 1) ? FL_QL : FL_QH);
                const uint32_t bB = sb + FL_K + bb*16384 + ((slab == 2) ? 8192 : 0);
#pragma unroll
                for (int kk = 0; kk < 4; kk++) {
                    uint32_t a[4][4], bf[4];
#pragma unroll
                    for (int mi = 0; mi < 4; mi++) {
                        uint32_t off = (uint32_t)((wm + mi*16 + lrow)*128 + kk*32 + lcb);
                        ldsm_x4(a[mi][0], a[mi][1], a[mi][2], a[mi][3], aB + sw128(off));
                    }
                    {
                        uint32_t off = (uint32_t)((wn + lrow)*128 + kk*32 + lcb);
                        ldsm_x4(bf[0], bf[1], bf[2], bf[3], bB + sw128(off));
                    }
#pragma unroll
                    for (int mi = 0; mi < 4; mi++) {
                        mma_bf16(acc[mi][0], a[mi], bf[0], bf[2]);
                        mma_bf16(acc[mi][1], a[mi], bf[1], bf[3]);
                    }
                }
            }
            // store raw scores to S[bb]
            float* st = smf + (FL_S + bb*34816) / 4;
#pragma unroll
            for (int mi = 0; mi < 4; mi++)
#pragma unroll
                for (int ni = 0; ni < 2; ni++) {
                    const int row = wm + mi*16 + r4;
                    const int col = wn + ni*8 + c2;
                    *(float2*)&st[row * 68 + col]       = make_float2(acc[mi][ni][0], acc[mi][ni][1]);
                    *(float2*)&st[(row + 8) * 68 + col] = make_float2(acc[mi][ni][2], acc[mi][ni][3]);
                }
            BAR_ARRIVE(1 + bb, 512);           // S[bb] full (BAR drains STS)

            if (t + 1 < T) {
                const int nb = bb ^ 1;
                if (t >= 1) BAR(3 + nb, 512);  // wait stage nb free
                const int k0n = (t + 1) * 64;
                for (int i = t2; i < 512; i += 256) {
                    int r = i >> 3, c = (i & 7) * 16;
                    uint32_t sw = sw128((uint32_t)(r*128 + c));
                    cp16(sb + FL_K + nb*16384 + sw,
                         (const char*)(Kh + base + (size_t)(k0n + r)*E_) + c);
                    cp16(sb + FL_K + nb*16384 + 8192 + sw,
                         (const char*)(Kl + base + (size_t)(k0n + r)*E_) + c);
                }
                for (int i = t2; i < 1024; i += 256) {
                    int r = i >> 4, c = (i & 15) * 16;
                    cp16(sb + FL_V + nb*17408 + (uint32_t)(r*272 + c),
                         (const char*)(V + base + (size_t)(k0n + r)*E_) + c);
                }
                CP_COMMIT();
                CP_WAIT0();
                BAR(5, 256);
            }
        }
    } else {
        // =================== FFMA GROUP (softmax + PV) ======================
        const int t2 = tid - 256;
        const int tx = t2 & 15;
        const int ty = t2 >> 4;
        const int tm = ty * 8;
        const int tn = tx * 4;

        float o[8][4];
        float m_i[8], l_i[8];
#pragma unroll
        for (int i = 0; i < 8; i++) {
            m_i[i] = -1e30f; l_i[i] = 0.f;
#pragma unroll
            for (int j = 0; j < 4; j++) o[i][j] = 0.f;
        }

        for (int t = 0; t < T; t++) {
            const int bb = t & 1;
            const int k0 = t * 64;
            BAR(1 + bb, 512);                 // wait S[bb] full
            float* SS = smf + (FL_S + bb*34816) / 4;
            float* SV = smf + (FL_V + bb*17408) / 4;

            float s[8][4];
#pragma unroll
            for (int i = 0; i < 8; i++) {
                float4 sv = *(const float4*)&SS[(tm + i) * 68 + tn];
                s[i][0] = sv.x; s[i][1] = sv.y; s[i][2] = sv.z; s[i][3] = sv.w;
            }

            if (k0 >= q0) {
#pragma unroll
                for (int i = 0; i < 8; i++)
#pragma unroll
                    for (int j = 0; j < 4; j++)
                        if (k0 + tn + j > q0 + tm + i) s[i][j] = -1e30f;
            }

#pragma unroll
            for (int i = 0; i < 8; i++) {
                float rm = fmaxf(fmaxf(s[i][0], s[i][1]), fmaxf(s[i][2], s[i][3]));
#pragma unroll
                for (int off = 8; off >= 1; off >>= 1)
                    rm = fmaxf(rm, __shfl_xor_sync(0xffffffffu, rm, off));
                float mnew = fmaxf(m_i[i], rm);
                float scal = fexp2((m_i[i] - mnew) * EXP_C);
                float sum = 0.f;
#pragma unroll
                for (int j = 0; j < 4; j++) {
                    s[i][j] = fexp2((s[i][j] - mnew) * EXP_C);
                    sum += s[i][j];
                }
#pragma unroll
                for (int off = 8; off >= 1; off >>= 1)
                    sum += __shfl_xor_sync(0xffffffffu, sum, off);
                l_i[i] = l_i[i] * scal + sum;
                m_i[i] = mnew;
#pragma unroll
                for (int j = 0; j < 4; j++) o[i][j] *= scal;
            }

            // write P in place; PV reads only own-warp rows -> warp sync only
#pragma unroll
            for (int i = 0; i < 8; i++)
                *(float4*)&SS[(tm + i) * 68 + tn] =
                    make_float4(s[i][0], s[i][1], s[i][2], s[i][3]);
            __syncwarp(0xffffffffu);

            // PV
#pragma unroll 4
            for (int k4 = 0; k4 < 64; k4 += 4) {
                float4 v0 = *(const float4*)&SV[(k4 + 0) * 68 + tn];
                float4 v1 = *(const float4*)&SV[(k4 + 1) * 68 + tn];
                float4 v2 = *(const float4*)&SV[(k4 + 2) * 68 + tn];
                float4 v3 = *(const float4*)&SV[(k4 + 3) * 68 + tn];
#pragma unroll
                for (int i = 0; i < 8; i++) {
                    float4 pr = *(const float4*)&SS[(tm + i) * 68 + k4];
                    o[i][0] = fmaf(pr.x, v0.x, o[i][0]);
                    o[i][1] = fmaf(pr.x, v0.y, o[i][1]);
                    o[i][2] = fmaf(pr.x, v0.z, o[i][2]);
                    o[i][3] = fmaf(pr.x, v0.w, o[i][3]);
                    o[i][0] = fmaf(pr.y, v1.x, o[i][0]);
                    o[i][1] = fmaf(pr.y, v1.y, o[i][1]);
                    o[i][2] = fmaf(pr.y, v1.z, o[i][2]);
                    o[i][3] = fmaf(pr.y, v1.w, o[i][3]);
                    o[i][0] = fmaf(pr.z, v2.x, o[i][0]);
                    o[i][1] = fmaf(pr.z, v2.y, o[i][1]);
                    o[i][2] = fmaf(pr.z, v2.z, o[i][2]);
                    o[i][3] = fmaf(pr.z, v2.w, o[i][3]);
                    o[i][0] = fmaf(pr.w, v3.x, o[i][0]);
                    o[i][1] = fmaf(pr.w, v3.y, o[i][1]);
                    o[i][2] = fmaf(pr.w, v3.z, o[i][2]);
                    o[i][3] = fmaf(pr.w, v3.w, o[i][3]);
                }
            }
            BAR_ARRIVE(3 + bb, 512);          // stage bb free
        }

        // epilogue: normalize + fp32 + bf16 hi/lo split
#pragma unroll
        for (int i = 0; i < 8; i++) {
            float inv = 1.f / l_i[i];
            float r0 = o[i][0] * inv, r1 = o[i][1] * inv;
            float r2 = o[i][2] * inv, r3 = o[i][3] * inv;
            size_t idx = base + (size_t)(q0 + tm + i) * E_ + tn;
            *(float4*)&O[idx] = make_float4(r0, r1, r2, r3);
            __nv_bfloat16 h0 = __float2bfloat16(r0);
            __nv_bfloat16 h1 = __float2bfloat16(r1);
            __nv_bfloat16 h2 = __float2bfloat16(r2);
            __nv_bfloat16 h3 = __float2bfloat16(r3);
            __nv_bfloat162 ph0; ph0.x = h0; ph0.y = h1;
            __nv_bfloat162 ph1; ph1.x = h2; ph1.y = h3;
            __nv_bfloat162 pl0;
            pl0.x = __float2bfloat16(r0 - __bfloat162float(h0));
            pl0.y = __float2bfloat16(r1 - __bfloat162float(h1));
            __nv_bfloat162 pl1;
            pl1.x = __float2bfloat16(r2 - __bfloat162float(h2));
            pl1.y = __float2bfloat16(r3 - __bfloat162float(h3));
            *(__nv_bfloat162*)&Ohi[idx]     = ph0;
            *(__nv_bfloat162*)&Ohi[idx + 2] = ph1;
            *(__nv_bfloat162*)&Olo[idx]     = pl0;
            *(__nv_bfloat162*)&Olo[idx + 2] = pl1;
        }
    }
}

// ---------------------------------------------------------------------------
extern "C" void kernel_launch(void* const* d_in, const int* in_sizes, int n_in,
                              void* d_out, int out_size)
{
    const float* query = (const float*)d_in[0];
    const float* key   = (const float*)d_in[1];
    const float* value = (const float*)d_in[2];
    // d_in[3] = mask (causal, structural) — unused
    const float* w_q = (const float*)d_in[4];
    const float* w_k = (const float*)d_in[5];
    const float* w_v = (const float*)d_in[6];
    const float* w_o = (const float*)d_in[7];
    float* out = (float*)d_out;

    float *Qb, *Kb, *Vb, *Ab;
    cudaGetSymbolAddress((void**)&Qb, g_Q);
    cudaGetSymbolAddress((void**)&Kb, g_K);
    cudaGetSymbolAddress((void**)&Vb, g_V);
    cudaGetSymbolAddress((void**)&Ab, g_A);
    __nv_bfloat16 *qh, *ql, *kh, *kl, *vh, *vl, *ah, *al, *wh, *wl;
    __nv_bfloat16 *pqh, *pql, *pkh, *pkl;
    cudaGetSymbolAddress((void**)&qh, g_qhi);
    cudaGetSymbolAddress((void**)&ql, g_qlo);
    cudaGetSymbolAddress((void**)&kh, g_khi);
    cudaGetSymbolAddress((void**)&kl, g_klo);
    cudaGetSymbolAddress((void**)&vh, g_vhi);
    cudaGetSymbolAddress((void**)&vl, g_vlo);
    cudaGetSymbolAddress((void**)&ah, g_ahi);
    cudaGetSymbolAddress((void**)&al, g_alo);
    cudaGetSymbolAddress((void**)&wh, g_whi);
    cudaGetSymbolAddress((void**)&wl, g_wlo);
    cudaGetSymbolAddress((void**)&pqh, g_pqh);
    cudaGetSymbolAddress((void**)&pql, g_pql);
    cudaGetSymbolAddress((void**)&pkh, g_pkh);
    cudaGetSymbolAddress((void**)&pkl, g_pkl);
    const int WSZ = E_*E_;

    cudaFuncSetAttribute(flash_ws,
                         cudaFuncAttributeMaxDynamicSharedMemorySize, FL_SMEM);
    cudaFuncSetAttribute(gemm_hybrid,
                         cudaFuncAttributeMaxDynamicSharedMemorySize, HY_DSMEM);
    cudaFuncSetAttribute(gemm_hybrid_qkv,
                         cudaFuncAttributeMaxDynamicSharedMemorySize, HY_DSMEM);

    const int actN4 = M_ * E_ / 4;
    const int wN4   = E_ * E_ / 4;

    split7<<<dim3(actN4/256, 7), 256>>>(query, key, value, w_q, w_k, w_v, w_o,
                                        qh, ql, kh, kl, vh, vl,
                                        wh + 0*WSZ, wl + 0*WSZ, wh + 1*WSZ, wl + 1*WSZ,
                                        wh + 2*WSZ, wl + 2*WSZ, wh + 3*WSZ, wl + 3*WSZ,
                                        actN4, wN4);

    gemm_hybrid_qkv<<<dim3(E_/128, M_/128, 3), 512, HY_DSMEM>>>(
        query, key, value, w_q, w_k, w_v,
        qh, ql, kh, kl, vh, vl,
        wh + 0*WSZ, wl + 0*WSZ, wh + 1*WSZ, wl + 1*WSZ, wh + 2*WSZ, wl + 2*WSZ,
        Qb, Kb, Vb, pqh, pql, pkh, pkl);

    flash_ws<<<dim3(S_/128, H_, B_), 512, FL_SMEM>>>(
        pqh, pql, pkh, pkl, Vb, Ab, ah, al);

    gemm_hybrid<<<dim3(E_/128, M_/128), 512, HY_DSMEM>>>(
        Ab, w_o, ah, al, wh + 3*WSZ, wl + 3*WSZ, out);
}